// round 15
// baseline (speedup 1.0000x reference)
#include <cuda_runtime.h>
#include <cuda.h>
#include <math.h>
#include <stdint.h>

#define B_   4
#define T_   2048
#define C_   1024
#define NH_  16
#define HD_  64
#define M_   (B_*T_)      // 8192
#define KW_  (C_/2)       // 512 packed words per K=1024 row

// Scratch (allocation-free: __device__ globals)
__device__ uint32_t g_qhi[B_*NH_*T_*HD_/2], g_qlo[B_*NH_*T_*HD_/2];  // fp16 split
__device__ uint32_t g_khi[B_*NH_*T_*HD_/2], g_klo[B_*NH_*T_*HD_/2];  // fp16 split
__device__ float    g_v  [B_*NH_*T_*HD_];
__device__ uint32_t g_xhi[M_*KW_],  g_xlo[M_*KW_];      // fp16 split x
__device__ uint32_t g_ahi[M_*KW_],  g_alo[M_*KW_];      // fp16 split attention out
__device__ uint32_t g_wthi[3*C_*KW_];                   // w_attn^T fp16
__device__ uint32_t g_wphi[C_*KW_];                     // w_proj^T fp16

// ===========================================================================
// Helpers
// ===========================================================================
// fp16 pair split (even in low 16)
__device__ __forceinline__ void split2h(float e, float o, uint32_t& hi, uint32_t& lo) {
    asm("cvt.rn.f16x2.f32 %0, %1, %2;" : "=r"(hi) : "f"(o), "f"(e));
    float he, ho;
    asm("{.reg .f16 a,b;\n\tmov.b32 {a,b}, %2;\n\tcvt.f32.f16 %0, a;\n\tcvt.f32.f16 %1, b;}"
        : "=f"(he), "=f"(ho) : "r"(hi));
    asm("cvt.rn.f16x2.f32 %0, %1, %2;" : "=r"(lo) : "f"(o - ho), "f"(e - he));
}
// fp16 pair round (hi only)
__device__ __forceinline__ uint32_t pack2h(float e, float o) {
    uint32_t hi;
    asm("cvt.rn.f16x2.f32 %0, %1, %2;" : "=r"(hi) : "f"(o), "f"(e));
    return hi;
}

#define MMA_F16(c, a0v, a1v, a2v, a3v, b0v, b1v) \
    asm volatile("mma.sync.aligned.m16n8k16.row.col.f32.f16.f16.f32 " \
        "{%0,%1,%2,%3}, {%4,%5,%6,%7}, {%8,%9}, {%0,%1,%2,%3};" \
        : "+f"((c)[0]), "+f"((c)[1]), "+f"((c)[2]), "+f"((c)[3]) \
        : "r"(a0v), "r"(a1v), "r"(a2v), "r"(a3v), "r"(b0v), "r"(b1v))

#define LDSM_X4(r0,r1,r2,r3, addr) \
    asm volatile("ldmatrix.sync.aligned.m8n8.x4.shared.b16 {%0,%1,%2,%3}, [%4];" \
        : "=r"(r0), "=r"(r1), "=r"(r2), "=r"(r3) : "r"(addr))
#define LDSM_X2(r0,r1, addr) \
    asm volatile("ldmatrix.sync.aligned.m8n8.x2.shared.b16 {%0,%1}, [%2];" \
        : "=r"(r0), "=r"(r1) : "r"(addr))

__device__ __forceinline__ uint32_t smem_u32(const void* p) {
    uint32_t a;
    asm("{ .reg .u64 t; cvta.to.shared.u64 t, %1; cvt.u32.u64 %0, t; }" : "=r"(a) : "l"(p));
    return a;
}
#define CP_ASYNC16(saddr, gptr) \
    asm volatile("cp.async.cg.shared.global [%0], [%1], 16;" :: "r"(saddr), "l"(gptr))
#define CP_COMMIT() asm volatile("cp.async.commit_group;" ::: "memory")
#define CP_WAIT(n)  asm volatile("cp.async.wait_group %0;" :: "n"(n) : "memory")

// ===========================================================================
// Prologue kernels
// ===========================================================================
__global__ __launch_bounds__(256)
void split_pack_elem_f16(const float* __restrict__ in, uint32_t* __restrict__ hi,
                         uint32_t* __restrict__ lo, int n4)
{
    int i = blockIdx.x * 256 + threadIdx.x;
    if (i < n4) {
        float4 v = ((const float4*)in)[i];
        uint2 h, l;
        split2h(v.x, v.y, h.x, l.x);
        split2h(v.z, v.w, h.y, l.y);
        ((uint2*)hi)[i] = h;
        ((uint2*)lo)[i] = l;
    }
}

// transpose + fp16 round (hi only): in [R=k][C=n] -> out[n][R/2 words]
__global__ __launch_bounds__(256)
void transpose_pack_f16(const float* __restrict__ in, uint32_t* __restrict__ ohi,
                        int R, int C)
{
    __shared__ float t[32][33];
    const int tx = threadIdx.x & 31, ty = (threadIdx.x >> 5) & 7;
    const int x0 = blockIdx.x * 32;
    const int y0 = blockIdx.y * 32;
#pragma unroll
    for (int i = 0; i < 32; i += 8)
        t[ty + i][tx] = in[(size_t)(y0 + ty + i) * C + x0 + tx];
    __syncthreads();
    const int Rw = R >> 1;
    const int wl = threadIdx.x & 15;
    const int nl = threadIdx.x >> 4;
#pragma unroll
    for (int half = 0; half < 2; half++) {
        const int n_l = nl + half * 16;
        ohi[(size_t)(x0 + n_l) * Rw + (y0 >> 1) + wl] =
            pack2h(t[2 * wl][n_l], t[2 * wl + 1][n_l]);
    }
}

// ===========================================================================
// fp16 2-term HMMA GEMM, high-occupancy variant:
//   CTA tile 128(M) x 64(N), 8 warps (4m x 2n), warp tile 32x32.
//   3 staged matrices (Ah, Al, Bh), single barrier per K chunk, 3 CTAs/SM.
// ===========================================================================
#define GLD 20
#define ASTG (128*GLD)               // words per A matrix per stage
#define BSTG (64*GLD)                // words per B matrix per stage
#define STG_W (2*ASTG + BSTG)        // 6400 words per stage
#define GEMM_SMEM (2*STG_W*4)        // 51200 B

template<int NTOT, bool QKV>
__global__ __launch_bounds__(256, 3)
void hmma_gemm(const uint32_t* __restrict__ Ahi, const uint32_t* __restrict__ Alo,
               const uint32_t* __restrict__ Bhi,
               const float* __restrict__ bias, float* __restrict__ out)
{
    extern __shared__ uint32_t smu[];
    const uint32_t sbase = smem_u32(smu);

    const int tid  = threadIdx.x;
    const int lane = tid & 31;
    const int wid  = tid >> 5;
    const int wm   = wid & 3;        // m quarter: 32 rows
    const int wn   = wid >> 2;       // n half: 32 cols
    const int m0   = blockIdx.y * 128;
    const int n0   = blockIdx.x * 64;
    const int g    = lane >> 2;
    const int tig  = lane & 3;

    const uint32_t* Ah_g = Ahi + (size_t)m0 * KW_;
    const uint32_t* Al_g = Alo + (size_t)m0 * KW_;
    const uint32_t* Bh_g = Bhi + (size_t)n0 * KW_;

    float acc[2][4][4];
#pragma unroll
    for (int i = 0; i < 2; i++)
#pragma unroll
        for (int j = 0; j < 4; j++)
#pragma unroll
            for (int e = 0; e < 4; e++) acc[i][j][e] = 0.f;

    const int crow = tid >> 2;          // 0..63
    const int cc4  = tid & 3;           // 4-word chunk

    const int sub  = lane >> 3, lrow = lane & 7;
    const int arow = (sub & 1) * 8 + lrow;
    const int acol = (sub >> 1) * 4;
    uint32_t awoff[2];
#pragma unroll
    for (int mt = 0; mt < 2; mt++)
        awoff[mt] = (uint32_t)((wm * 32 + mt * 16 + arow) * GLD + acol);
    const int bsub = (lane >> 3) & 1;
    uint32_t bwoff[4];
#pragma unroll
    for (int nt = 0; nt < 4; nt++)
        bwoff[nt] = (uint32_t)((wn * 32 + nt * 8 + lrow) * GLD + bsub * 4);

    // prologue: submit stage 0
    {
#pragma unroll
        for (int i = 0; i < 2; i++) {
            const int row = crow + i * 64;
            const uint32_t so = (uint32_t)(row * GLD + cc4 * 4) * 4u;
            CP_ASYNC16(sbase + so,            Ah_g + (size_t)row * KW_ + cc4 * 4);
            CP_ASYNC16(sbase + ASTG*4 + so,   Al_g + (size_t)row * KW_ + cc4 * 4);
        }
        CP_ASYNC16(sbase + 2*ASTG*4 + (uint32_t)(crow * GLD + cc4 * 4) * 4u,
                   Bh_g + (size_t)crow * KW_ + cc4 * 4);
        CP_COMMIT();
    }

#pragma unroll 1
    for (int kc = 0; kc < 32; kc++) {
        CP_WAIT(0);
        __syncthreads();

        if (kc + 1 < 32) {
            const uint32_t stg = sbase + ((kc + 1) & 1) * STG_W * 4;
#pragma unroll
            for (int i = 0; i < 2; i++) {
                const int row = crow + i * 64;
                const uint32_t so = (uint32_t)(row * GLD + cc4 * 4) * 4u;
                CP_ASYNC16(stg + so,          Ah_g + (size_t)row * KW_ + (kc + 1) * 16 + cc4 * 4);
                CP_ASYNC16(stg + ASTG*4 + so, Al_g + (size_t)row * KW_ + (kc + 1) * 16 + cc4 * 4);
            }
            CP_ASYNC16(stg + 2*ASTG*4 + (uint32_t)(crow * GLD + cc4 * 4) * 4u,
                       Bh_g + (size_t)crow * KW_ + (kc + 1) * 16 + cc4 * 4);
            CP_COMMIT();
        }

        const uint32_t stg = sbase + (kc & 1) * STG_W * 4;
        const uint32_t bAh = stg;
        const uint32_t bAl = stg + ASTG * 4;
        const uint32_t bBh = stg + 2 * ASTG * 4;

#pragma unroll
        for (int ks = 0; ks < 2; ks++) {
            const uint32_t k0w = ks * 8;
            uint32_t ah[2][4], al[2][4];
#pragma unroll
            for (int mt = 0; mt < 2; mt++) {
                LDSM_X4(ah[mt][0], ah[mt][1], ah[mt][2], ah[mt][3],
                        bAh + (awoff[mt] + k0w) * 4u);
                LDSM_X4(al[mt][0], al[mt][1], al[mt][2], al[mt][3],
                        bAl + (awoff[mt] + k0w) * 4u);
            }
#pragma unroll
            for (int nt = 0; nt < 4; nt++) {
                uint32_t bh0, bh1;
                LDSM_X2(bh0, bh1, bBh + (bwoff[nt] + k0w) * 4u);
#pragma unroll
                for (int mt = 0; mt < 2; mt++)
                    MMA_F16(acc[mt][nt], ah[mt][0], ah[mt][1], ah[mt][2], ah[mt][3], bh0, bh1);
#pragma unroll
                for (int mt = 0; mt < 2; mt++)
                    MMA_F16(acc[mt][nt], al[mt][0], al[mt][1], al[mt][2], al[mt][3], bh0, bh1);
            }
        }
    }

    // ---- epilogue ----
#pragma unroll
    for (int mt = 0; mt < 2; mt++) {
#pragma unroll
        for (int nt = 0; nt < 4; nt++) {
            const int n = n0 + wn * 32 + nt * 8 + tig * 2;
            const float bx = bias[n], by = bias[n + 1];
#pragma unroll
            for (int half = 0; half < 2; half++) {
                const int m = m0 + wm * 32 + mt * 16 + g + half * 8;
                const float vx = acc[mt][nt][half * 2 + 0] + bx;
                const float vy = acc[mt][nt][half * 2 + 1] + by;
                if (QKV) {
                    const int bb = m >> 11;
                    const int tt = m & (T_ - 1);
                    const int which = n >> 10;
                    const int cc = n & (C_ - 1);
                    const int h = cc >> 6;
                    const int d = cc & (HD_ - 1);
                    const size_t base = ((size_t)(bb * NH_ + h) * T_ + tt);
                    if (which == 2) {
                        float2 v; v.x = vx; v.y = vy;
                        *(float2*)&g_v[base * HD_ + d] = v;
                    } else {
                        uint32_t hw, lw;
                        split2h(vx, vy, hw, lw);
                        const size_t idx = base * (HD_/2) + (d >> 1);
                        if (which == 0) { g_qhi[idx] = hw; g_qlo[idx] = lw; }
                        else            { g_khi[idx] = hw; g_klo[idx] = lw; }
                    }
                } else {
                    float2 v; v.x = vx; v.y = vy;
                    *(float2*)&out[(size_t)m * NTOT + n] = v;
                }
            }
        }
    }
}

// ===========================================================================
// fp16 HMMA flash attention v6 (unchanged from R14):
//   QK^T 3-term fp16, PV 2-term fp16 with single-fp16 V.
//   FA2 register softmax, cp.async K, reg-prefetched V, tail-packed grid.
// ===========================================================================
#define FQ_LD 36
#define FV_LD 72
#define FL_SMEM (16128 * 4)

__global__ __launch_bounds__(256, 2)
void flash_hmma()
{
    extern __shared__ uint32_t smu[];
    const uint32_t sm_base = smem_u32(smu);
    uint32_t* Qh = smu;
    uint32_t* Ql = smu + 4608;

    const uint32_t bQh = sm_base;
    const uint32_t bQl = sm_base + 4608 * 4;
    const uint32_t kbase[2] = { sm_base + 9216 * 4, sm_base + 11520 * 4 };
    const uint32_t vword[2] = { 13824u, 14976u };

    const int tid  = threadIdx.x;
    const int lane = tid & 31;
    const int wm   = tid >> 5;
    const int g    = lane >> 2;
    const int tig  = lane & 3;

    const int bh = blockIdx.x;
    const int qi = 15 - blockIdx.y;
    const int q0 = qi * 128;

    const uint32_t* Qgh = g_qhi + (size_t)bh * T_ * 32 + (size_t)q0 * 32;
    const uint32_t* Qgl = g_qlo + (size_t)bh * T_ * 32 + (size_t)q0 * 32;
    const uint32_t* Kgh = g_khi + (size_t)bh * T_ * 32;
    const uint32_t* Kgl = g_klo + (size_t)bh * T_ * 32;
    const float*    Vg  = g_v   + (size_t)bh * T_ * HD_;

    const int sub  = lane >> 3, lrow = lane & 7;

    uint32_t kwoff4[2];
#pragma unroll
    for (int np = 0; np < 2; np++)
        kwoff4[np] = (uint32_t)((np * 16 + (sub >> 1) * 8 + lrow) * FQ_LD + (sub & 1) * 4);

    const int km = tid >> 7, kr = (tid >> 2) & 31, kcc = tid & 3;
    const uint32_t kdst = (uint32_t)((km ? 1152 : 0) + kr * FQ_LD + kcc * 8) * 4u;
    const uint32_t* kgsrc = km ? Kgl : Kgh;

    const int pr = tid >> 4, d4 = tid & 15;

    const int nkt = 4 * qi + 4;

    // prologue: stage Q, submit K(0), prefetch V(0)
#pragma unroll
    for (int it = 0; it < 4; it++) {
        const int u = tid + it * 256;
        const int r = u >> 3, wc = (u & 7) * 4;
        *(uint4*)&Qh[r * FQ_LD + wc] = *(const uint4*)(Qgh + r * 32 + wc);
        *(uint4*)&Ql[r * FQ_LD + wc] = *(const uint4*)(Qgl + r * 32 + wc);
    }
    CP_ASYNC16(kbase[0] + kdst,      kgsrc + (size_t)kr * 32 + kcc * 8);
    CP_ASYNC16(kbase[0] + kdst + 16, kgsrc + (size_t)kr * 32 + kcc * 8 + 4);
    CP_COMMIT();
    float4 va = *(const float4*)(Vg + (size_t)(2 * pr)     * HD_ + d4 * 4);
    float4 vb = *(const float4*)(Vg + (size_t)(2 * pr + 1) * HD_ + d4 * 4);

    const int rlo = wm * 16 + g;
    const int rhi = rlo + 8;
    __syncthreads();

    // hoist Q fragments (loop-invariant)
    uint32_t qah[4][4], qal[4][4];
    {
        const uint32_t qwoff =
            (uint32_t)((wm * 16 + (sub & 1) * 8 + lrow) * FQ_LD + (sub >> 1) * 4);
#pragma unroll
        for (int ks = 0; ks < 4; ks++) {
            LDSM_X4(qah[ks][0], qah[ks][1], qah[ks][2], qah[ks][3],
                    bQh + (qwoff + ks * 8) * 4u);
            LDSM_X4(qal[ks][0], qal[ks][1], qal[ks][2], qal[ks][3],
                    bQl + (qwoff + ks * 8) * 4u);
        }
    }

    float o[8][4];
#pragma unroll
    for (int nt = 0; nt < 8; nt++)
#pragma unroll
        for (int e = 0; e < 4; e++) o[nt][e] = 0.f;

    float mrun_lo = -INFINITY, mrun_hi = -INFINITY;
    float lrun_lo = 0.f,       lrun_hi = 0.f;

    const int qrow_lo = q0 + rlo;
    const int qrow_hi = q0 + rhi;

#pragma unroll 1
    for (int kt = 0; kt < nkt; kt++) {
        {
            uint32_t* Vp = smu + vword[kt & 1];
            uint4 h;
            h.x = pack2h(va.x, vb.x);
            h.y = pack2h(va.y, vb.y);
            h.z = pack2h(va.z, vb.z);
            h.w = pack2h(va.w, vb.w);
            *(uint4*)&Vp[pr * FV_LD + d4 * 4] = h;
        }
        CP_WAIT(0);
        __syncthreads();

        if (kt + 1 < nkt) {
            CP_ASYNC16(kbase[(kt + 1) & 1] + kdst,
                       kgsrc + (size_t)((kt + 1) * 32 + kr) * 32 + kcc * 8);
            CP_ASYNC16(kbase[(kt + 1) & 1] + kdst + 16,
                       kgsrc + (size_t)((kt + 1) * 32 + kr) * 32 + kcc * 8 + 4);
            CP_COMMIT();
            va = *(const float4*)(Vg + (size_t)((kt + 1) * 32 + 2 * pr)     * HD_ + d4 * 4);
            vb = *(const float4*)(Vg + (size_t)((kt + 1) * 32 + 2 * pr + 1) * HD_ + d4 * 4);
        }

        const uint32_t bKh = kbase[kt & 1];
        const uint32_t bKl = bKh + 1152 * 4;
        const uint32_t* Vp = smu + vword[kt & 1];

        // ---- S = Q @ K^T : 3-term fp16 ----
        float s[4][4];
#pragma unroll
        for (int nt = 0; nt < 4; nt++)
#pragma unroll
            for (int e = 0; e < 4; e++) s[nt][e] = 0.f;

#pragma unroll
        for (int ks = 0; ks < 4; ks++) {
#pragma unroll
            for (int np = 0; np < 2; np++) {
                uint32_t bh0, bh1, bh2, bh3, bl0, bl1, bl2, bl3;
                LDSM_X4(bh0, bh1, bh2, bh3, bKh + (kwoff4[np] + ks * 8) * 4u);
                LDSM_X4(bl0, bl1, bl2, bl3, bKl + (kwoff4[np] + ks * 8) * 4u);
                MMA_F16(s[2*np],   qah[ks][0], qah[ks][1], qah[ks][2], qah[ks][3], bh0, bh1);
                MMA_F16(s[2*np+1], qah[ks][0], qah[ks][1], qah[ks][2], qah[ks][3], bh2, bh3);
                MMA_F16(s[2*np],   qal[ks][0], qal[ks][1], qal[ks][2], qal[ks][3], bh0, bh1);
                MMA_F16(s[2*np+1], qal[ks][0], qal[ks][1], qal[ks][2], qal[ks][3], bh2, bh3);
                MMA_F16(s[2*np],   qah[ks][0], qah[ks][1], qah[ks][2], qah[ks][3], bl0, bl1);
                MMA_F16(s[2*np+1], qah[ks][0], qah[ks][1], qah[ks][2], qah[ks][3], bl2, bl3);
            }
        }

        // ---- scale + causal mask + row max ----
        float mlo = -INFINITY, mhi = -INFINITY;
        const bool needmask = (kt * 32 + 31) > (q0 + wm * 16);
#pragma unroll
        for (int nt = 0; nt < 4; nt++) {
            const int colb = kt * 32 + nt * 8 + 2 * tig;
#pragma unroll
            for (int j = 0; j < 2; j++) {
                float v0 = s[nt][j] * 0.125f;
                float v1 = s[nt][2 + j] * 0.125f;
                if (needmask) {
                    if (colb + j > qrow_lo) v0 = -INFINITY;
                    if (colb + j > qrow_hi) v1 = -INFINITY;
                }
                s[nt][j] = v0;
                s[nt][2 + j] = v1;
                mlo = fmaxf(mlo, v0);
                mhi = fmaxf(mhi, v1);
            }
        }
#pragma unroll
        for (int off = 1; off < 4; off <<= 1) {
            mlo = fmaxf(mlo, __shfl_xor_sync(0xffffffffu, mlo, off));
            mhi = fmaxf(mhi, __shfl_xor_sync(0xffffffffu, mhi, off));
        }

        // ---- online softmax (registers) ----
        const float mnew_lo = fmaxf(mrun_lo, mlo);
        const float mnew_hi = fmaxf(mrun_hi, mhi);
        const float corr_lo = __expf(mrun_lo - mnew_lo);
        const float corr_hi = __expf(mrun_hi - mnew_hi);
        mrun_lo = mnew_lo; mrun_hi = mnew_hi;

        float sumlo = 0.f, sumhi = 0.f;
        uint32_t pah[2][4], pal[2][4];
#pragma unroll
        for (int nt = 0; nt < 4; nt++) {
            float p0 = __expf(s[nt][0] - mnew_lo);
            float p1 = __expf(s[nt][1] - mnew_lo);
            float p2 = __expf(s[nt][2] - mnew_hi);
            float p3 = __expf(s[nt][3] - mnew_hi);
            sumlo += p0 + p1;
            sumhi += p2 + p3;
            const int ks = nt >> 1;
            const int hi2 = (nt & 1) * 2;
            split2h(p0, p1, pah[ks][hi2],     pal[ks][hi2]);
            split2h(p2, p3, pah[ks][hi2 + 1], pal[ks][hi2 + 1]);
        }
#pragma unroll
        for (int off = 1; off < 4; off <<= 1) {
            sumlo += __shfl_xor_sync(0xffffffffu, sumlo, off);
            sumhi += __shfl_xor_sync(0xffffffffu, sumhi, off);
        }
        lrun_lo = lrun_lo * corr_lo + sumlo;
        lrun_hi = lrun_hi * corr_hi + sumhi;

#pragma unroll
        for (int nt = 0; nt < 8; nt++) {
            o[nt][0] *= corr_lo; o[nt][1] *= corr_lo;
            o[nt][2] *= corr_hi; o[nt][3] *= corr_hi;
        }

        // ---- O += P @ V : 2-term fp16, single-fp16 V ----
#pragma unroll
        for (int ks = 0; ks < 2; ks++) {
#pragma unroll
            for (int nt = 0; nt < 8; nt++) {
                const int col = nt * 8 + g;
                const uint32_t vh0 = Vp[(ks * 8 + tig)     * FV_LD + col];
                const uint32_t vh1 = Vp[(ks * 8 + tig + 4) * FV_LD + col];
                MMA_F16(o[nt], pah[ks][0], pah[ks][1], pah[ks][2], pah[ks][3], vh0, vh1);
                MMA_F16(o[nt], pal[ks][0], pal[ks][1], pal[ks][2], pal[ks][3], vh0, vh1);
            }
        }
    }

    // ---- normalize + store fp16-split output ----
    const float inv_lo = 1.f / lrun_lo;
    const float inv_hi = 1.f / lrun_hi;
    const int b = bh >> 4, h = bh & 15;
    const int t_lo = q0 + rlo, t_hi = q0 + rhi;
#pragma unroll
    for (int nt = 0; nt < 8; nt++) {
        const int d = nt * 8 + 2 * tig;
        const int w = (h * HD_ + d) >> 1;
        uint32_t hw, lw;
        split2h(o[nt][0] * inv_lo, o[nt][1] * inv_lo, hw, lw);
        g_ahi[(size_t)(b * T_ + t_lo) * KW_ + w] = hw;
        g_alo[(size_t)(b * T_ + t_lo) * KW_ + w] = lw;
        split2h(o[nt][2] * inv_hi, o[nt][3] * inv_hi, hw, lw);
        g_ahi[(size_t)(b * T_ + t_hi) * KW_ + w] = hw;
        g_alo[(size_t)(b * T_ + t_hi) * KW_ + w] = lw;
    }
}

// ===========================================================================
// Launch
// ===========================================================================
extern "C" void kernel_launch(void* const* d_in, const int* in_sizes, int n_in,
                              void* d_out, int out_size)
{
    const float* x      = (const float*)d_in[0];
    const float* w_attn = (const float*)d_in[1];
    const float* b_attn = (const float*)d_in[2];
    const float* w_proj = (const float*)d_in[3];
    const float* b_proj = (const float*)d_in[4];
    float* out = (float*)d_out;

    uint32_t *xhi, *xlo, *ahi, *alo, *wthi, *wphi;
    cudaGetSymbolAddress((void**)&xhi,  g_xhi);
    cudaGetSymbolAddress((void**)&xlo,  g_xlo);
    cudaGetSymbolAddress((void**)&ahi,  g_ahi);
    cudaGetSymbolAddress((void**)&alo,  g_alo);
    cudaGetSymbolAddress((void**)&wthi, g_wthi);
    cudaGetSymbolAddress((void**)&wphi, g_wphi);

    cudaFuncSetAttribute(flash_hmma,
                         cudaFuncAttributeMaxDynamicSharedMemorySize, FL_SMEM);
    cudaFuncSetAttribute(hmma_gemm<3072, true>,
                         cudaFuncAttributeMaxDynamicSharedMemorySize, GEMM_SMEM);
    cudaFuncSetAttribute(hmma_gemm<1024, false>,
                         cudaFuncAttributeMaxDynamicSharedMemorySize, GEMM_SMEM);

    // Prologue: fp16-split x; fp16-round both transposed weights
    split_pack_elem_f16<<<(M_*C_/4 + 255)/256, 256>>>(x, xhi, xlo, M_*C_/4);
    transpose_pack_f16<<<dim3(3072/32, 1024/32), 256>>>(w_attn, wthi, 1024, 3072);
    transpose_pack_f16<<<dim3(1024/32, 1024/32), 256>>>(w_proj, wphi, 1024, 1024);

    // QKV GEMM (fp16 2-term, CTA 128x64)
    hmma_gemm<3072, true><<<dim3(3072/64, M_/128), 256, GEMM_SMEM>>>(
        xhi, xlo, wthi, b_attn, nullptr);

    // Flash attention (fp16), tail-packed grid
    flash_hmma<<<dim3(B_*NH_, T_/128), 256, FL_SMEM>>>();

    // Output projection (fp16 2-term, CTA 128x64)
    hmma_gemm<1024, false><<<dim3(1024/64, M_/128), 256, GEMM_SMEM>>>(
        ahi, alo, wphi, b_proj, out);
}

// round 16
// speedup vs baseline: 1.0246x; 1.0246x over previous
#include <cuda_runtime.h>
#include <cuda.h>
#include <math.h>
#include <stdint.h>

#define B_   4
#define T_   2048
#define C_   1024
#define NH_  16
#define HD_  64
#define M_   (B_*T_)      // 8192
#define KW_  (C_/2)       // 512 packed words per K=1024 row

// Scratch (allocation-free: __device__ globals)
__device__ uint32_t g_qhi[B_*NH_*T_*HD_/2], g_qlo[B_*NH_*T_*HD_/2];  // fp16 split
__device__ uint32_t g_khi[B_*NH_*T_*HD_/2], g_klo[B_*NH_*T_*HD_/2];  // fp16 split
__device__ float    g_v  [B_*NH_*T_*HD_];                            // fp32 V
__device__ uint32_t g_vp [B_*NH_*(T_/2)*HD_];                        // fp16 pair-packed V
__device__ uint32_t g_xhi[M_*KW_],  g_xlo[M_*KW_];      // fp16 split x
__device__ uint32_t g_ahi[M_*KW_],  g_alo[M_*KW_];      // fp16 split attention out
__device__ uint32_t g_wthi[3*C_*KW_];                   // w_attn^T fp16
__device__ uint32_t g_wphi[C_*KW_];                     // w_proj^T fp16

// ===========================================================================
// Helpers
// ===========================================================================
// fp16 pair split (even in low 16)
__device__ __forceinline__ void split2h(float e, float o, uint32_t& hi, uint32_t& lo) {
    asm("cvt.rn.f16x2.f32 %0, %1, %2;" : "=r"(hi) : "f"(o), "f"(e));
    float he, ho;
    asm("{.reg .f16 a,b;\n\tmov.b32 {a,b}, %2;\n\tcvt.f32.f16 %0, a;\n\tcvt.f32.f16 %1, b;}"
        : "=f"(he), "=f"(ho) : "r"(hi));
    asm("cvt.rn.f16x2.f32 %0, %1, %2;" : "=r"(lo) : "f"(o - ho), "f"(e - he));
}
// fp16 pair round (hi only)
__device__ __forceinline__ uint32_t pack2h(float e, float o) {
    uint32_t hi;
    asm("cvt.rn.f16x2.f32 %0, %1, %2;" : "=r"(hi) : "f"(o), "f"(e));
    return hi;
}

#define MMA_F16(c, a0v, a1v, a2v, a3v, b0v, b1v) \
    asm volatile("mma.sync.aligned.m16n8k16.row.col.f32.f16.f16.f32 " \
        "{%0,%1,%2,%3}, {%4,%5,%6,%7}, {%8,%9}, {%0,%1,%2,%3};" \
        : "+f"((c)[0]), "+f"((c)[1]), "+f"((c)[2]), "+f"((c)[3]) \
        : "r"(a0v), "r"(a1v), "r"(a2v), "r"(a3v), "r"(b0v), "r"(b1v))

#define LDSM_X4(r0,r1,r2,r3, addr) \
    asm volatile("ldmatrix.sync.aligned.m8n8.x4.shared.b16 {%0,%1,%2,%3}, [%4];" \
        : "=r"(r0), "=r"(r1), "=r"(r2), "=r"(r3) : "r"(addr))
#define LDSM_X2(r0,r1, addr) \
    asm volatile("ldmatrix.sync.aligned.m8n8.x2.shared.b16 {%0,%1}, [%2];" \
        : "=r"(r0), "=r"(r1) : "r"(addr))

__device__ __forceinline__ uint32_t smem_u32(const void* p) {
    uint32_t a;
    asm("{ .reg .u64 t; cvta.to.shared.u64 t, %1; cvt.u32.u64 %0, t; }" : "=r"(a) : "l"(p));
    return a;
}
#define CP_ASYNC16(saddr, gptr) \
    asm volatile("cp.async.cg.shared.global [%0], [%1], 16;" :: "r"(saddr), "l"(gptr))
#define CP_COMMIT() asm volatile("cp.async.commit_group;" ::: "memory")
#define CP_WAIT(n)  asm volatile("cp.async.wait_group %0;" :: "n"(n) : "memory")

// ===========================================================================
// Prologue kernels
// ===========================================================================
__global__ __launch_bounds__(256)
void split_pack_elem_f16(const float* __restrict__ in, uint32_t* __restrict__ hi,
                         uint32_t* __restrict__ lo, int n4)
{
    int i = blockIdx.x * 256 + threadIdx.x;
    if (i < n4) {
        float4 v = ((const float4*)in)[i];
        uint2 h, l;
        split2h(v.x, v.y, h.x, l.x);
        split2h(v.z, v.w, h.y, l.y);
        ((uint2*)hi)[i] = h;
        ((uint2*)lo)[i] = l;
    }
}

// transpose + fp16 round (hi only): in [R=k][C=n] -> out[n][R/2 words]
__global__ __launch_bounds__(256)
void transpose_pack_f16(const float* __restrict__ in, uint32_t* __restrict__ ohi,
                        int R, int C)
{
    __shared__ float t[32][33];
    const int tx = threadIdx.x & 31, ty = (threadIdx.x >> 5) & 7;
    const int x0 = blockIdx.x * 32;
    const int y0 = blockIdx.y * 32;
#pragma unroll
    for (int i = 0; i < 32; i += 8)
        t[ty + i][tx] = in[(size_t)(y0 + ty + i) * C + x0 + tx];
    __syncthreads();
    const int Rw = R >> 1;
    const int wl = threadIdx.x & 15;
    const int nl = threadIdx.x >> 4;
#pragma unroll
    for (int half = 0; half < 2; half++) {
        const int n_l = nl + half * 16;
        ohi[(size_t)(x0 + n_l) * Rw + (y0 >> 1) + wl] =
            pack2h(t[2 * wl][n_l], t[2 * wl + 1][n_l]);
    }
}

// pair-pack V along T: vp[tp*HD + d] = f16x2(V[2tp][d] lo, V[2tp+1][d] hi)
__global__ __launch_bounds__(256)
void pairpack_v(const float* __restrict__ v, uint32_t* __restrict__ vp, int n4)
{
    int i = blockIdx.x * 256 + threadIdx.x;
    if (i < n4) {
        const int w = i * 4;
        const int d = w & (HD_ - 1);
        const int tp = w >> 6;               // global pair index (T even, never crosses bh)
        const float* r0 = v + (size_t)tp * 2 * HD_ + d;
        float4 a = *(const float4*)r0;
        float4 b = *(const float4*)(r0 + HD_);
        uint4 h;
        h.x = pack2h(a.x, b.x);
        h.y = pack2h(a.y, b.y);
        h.z = pack2h(a.z, b.z);
        h.w = pack2h(a.w, b.w);
        *(uint4*)(vp + w) = h;
    }
}

// ===========================================================================
// fp16 2-term HMMA GEMM (R14 config): CTA 128x128, 8 warps (2m x 4n),
//   3 staged matrices (Ah, Al, Bh), single barrier per K chunk, 2 CTAs/SM.
// ===========================================================================
#define GLD 20
#define GSTG (128*GLD)
#define GEMM_SMEM (6*GSTG*4)    // 61440

template<int NTOT, bool QKV>
__global__ __launch_bounds__(256, 2)
void hmma_gemm(const uint32_t* __restrict__ Ahi, const uint32_t* __restrict__ Alo,
               const uint32_t* __restrict__ Bhi,
               const float* __restrict__ bias, float* __restrict__ out)
{
    extern __shared__ uint32_t smu[];
    const uint32_t sbase = smem_u32(smu);

    const int tid  = threadIdx.x;
    const int lane = tid & 31;
    const int wid  = tid >> 5;
    const int wm   = wid & 1;
    const int wn   = wid >> 1;
    const int m0   = blockIdx.y * 128;
    const int n0   = blockIdx.x * 128;
    const int g    = lane >> 2;
    const int tig  = lane & 3;

    const uint32_t* src[3];
    src[0] = Ahi + (size_t)m0 * KW_;
    src[1] = Alo + (size_t)m0 * KW_;
    src[2] = Bhi + (size_t)n0 * KW_;

    float acc[4][4][4];
#pragma unroll
    for (int i = 0; i < 4; i++)
#pragma unroll
        for (int j = 0; j < 4; j++)
#pragma unroll
            for (int e = 0; e < 4; e++) acc[i][j][e] = 0.f;

    const int crow = tid >> 2;
    const int cc4  = tid & 3;

    const int sub  = lane >> 3, lrow = lane & 7;
    const int arow = (sub & 1) * 8 + lrow;
    const int acol = (sub >> 1) * 4;
    uint32_t awoff[4];
#pragma unroll
    for (int mt = 0; mt < 4; mt++)
        awoff[mt] = (uint32_t)((wm * 64 + mt * 16 + arow) * GLD + acol);
    const int bsub = (lane >> 3) & 1;
    uint32_t bwoff[4];
#pragma unroll
    for (int nt = 0; nt < 4; nt++)
        bwoff[nt] = (uint32_t)((wn * 32 + nt * 8 + lrow) * GLD + bsub * 4);

    // prologue: submit stage 0
    {
#pragma unroll
        for (int m = 0; m < 3; m++)
#pragma unroll
            for (int i = 0; i < 2; i++) {
                const int row = crow + i * 64;
                const uint32_t so = sbase + (uint32_t)(m * GSTG + row * GLD + cc4 * 4) * 4u;
                CP_ASYNC16(so, src[m] + (size_t)row * KW_ + cc4 * 4);
            }
        CP_COMMIT();
    }

#pragma unroll 1
    for (int kc = 0; kc < 32; kc++) {
        CP_WAIT(0);
        __syncthreads();

        if (kc + 1 < 32) {
            const uint32_t stg = sbase + ((kc + 1) & 1) * 3 * GSTG * 4;
#pragma unroll
            for (int m = 0; m < 3; m++)
#pragma unroll
                for (int i = 0; i < 2; i++) {
                    const int row = crow + i * 64;
                    const uint32_t so = stg + (uint32_t)(m * GSTG + row * GLD + cc4 * 4) * 4u;
                    CP_ASYNC16(so, src[m] + (size_t)row * KW_ + (kc + 1) * 16 + cc4 * 4);
                }
            CP_COMMIT();
        }

        const uint32_t stg = sbase + (kc & 1) * 3 * GSTG * 4;
        const uint32_t bAh = stg;
        const uint32_t bAl = stg + GSTG * 4;
        const uint32_t bBh = stg + 2 * GSTG * 4;

#pragma unroll
        for (int ks = 0; ks < 2; ks++) {
            const uint32_t k0w = ks * 8;
            uint32_t ah[4][4], al[4][4];
#pragma unroll
            for (int mt = 0; mt < 4; mt++) {
                LDSM_X4(ah[mt][0], ah[mt][1], ah[mt][2], ah[mt][3],
                        bAh + (awoff[mt] + k0w) * 4u);
                LDSM_X4(al[mt][0], al[mt][1], al[mt][2], al[mt][3],
                        bAl + (awoff[mt] + k0w) * 4u);
            }
#pragma unroll
            for (int nt = 0; nt < 4; nt++) {
                uint32_t bh0, bh1;
                LDSM_X2(bh0, bh1, bBh + (bwoff[nt] + k0w) * 4u);
#pragma unroll
                for (int mt = 0; mt < 4; mt++)
                    MMA_F16(acc[mt][nt], ah[mt][0], ah[mt][1], ah[mt][2], ah[mt][3], bh0, bh1);
#pragma unroll
                for (int mt = 0; mt < 4; mt++)
                    MMA_F16(acc[mt][nt], al[mt][0], al[mt][1], al[mt][2], al[mt][3], bh0, bh1);
            }
        }
    }

    // ---- epilogue ----
#pragma unroll
    for (int mt = 0; mt < 4; mt++) {
#pragma unroll
        for (int nt = 0; nt < 4; nt++) {
            const int n = n0 + wn * 32 + nt * 8 + tig * 2;
            const float bx = bias[n], by = bias[n + 1];
#pragma unroll
            for (int half = 0; half < 2; half++) {
                const int m = m0 + wm * 64 + mt * 16 + g + half * 8;
                const float vx = acc[mt][nt][half * 2 + 0] + bx;
                const float vy = acc[mt][nt][half * 2 + 1] + by;
                if (QKV) {
                    const int bb = m >> 11;
                    const int tt = m & (T_ - 1);
                    const int which = n >> 10;
                    const int cc = n & (C_ - 1);
                    const int h = cc >> 6;
                    const int d = cc & (HD_ - 1);
                    const size_t base = ((size_t)(bb * NH_ + h) * T_ + tt);
                    if (which == 2) {
                        float2 v; v.x = vx; v.y = vy;
                        *(float2*)&g_v[base * HD_ + d] = v;
                    } else {
                        uint32_t hw, lw;
                        split2h(vx, vy, hw, lw);
                        const size_t idx = base * (HD_/2) + (d >> 1);
                        if (which == 0) { g_qhi[idx] = hw; g_qlo[idx] = lw; }
                        else            { g_khi[idx] = hw; g_klo[idx] = lw; }
                    }
                } else {
                    float2 v; v.x = vx; v.y = vy;
                    *(float2*)&out[(size_t)m * NTOT + n] = v;
                }
            }
        }
    }
}

// ===========================================================================
// fp16 HMMA flash attention v7:
//   QK^T 3-term fp16, PV 2-term fp16 with pre-packed fp16 V.
//   K AND V both cp.async double-buffered (one commit group per tile).
//   FA2 register softmax, tail-packed grid.
// Smem (words): Qh 0(4608) Ql 4608 | Kbuf0 9216 Kbuf1 11520 (Kh 1152 + Kl 1152)
//   | Vbuf0 13824(1152) Vbuf1 14976 -> 16128 words = 64512 B
// ===========================================================================
#define FQ_LD 36
#define FV_LD 72
#define FL_SMEM (16128 * 4)

__global__ __launch_bounds__(256, 2)
void flash_hmma()
{
    extern __shared__ uint32_t smu[];
    const uint32_t sm_base = smem_u32(smu);
    uint32_t* Qh = smu;
    uint32_t* Ql = smu + 4608;

    const uint32_t bQh = sm_base;
    const uint32_t bQl = sm_base + 4608 * 4;
    const uint32_t kbase[2] = { sm_base + 9216 * 4, sm_base + 11520 * 4 };
    const uint32_t vbase[2] = { sm_base + 13824 * 4, sm_base + 14976 * 4 };
    const uint32_t vword[2] = { 13824u, 14976u };

    const int tid  = threadIdx.x;
    const int lane = tid & 31;
    const int wm   = tid >> 5;
    const int g    = lane >> 2;
    const int tig  = lane & 3;

    const int bh = blockIdx.x;            // 0..63
    const int qi = 15 - blockIdx.y;       // big qi scheduled first
    const int q0 = qi * 128;

    const uint32_t* Qgh = g_qhi + (size_t)bh * T_ * 32 + (size_t)q0 * 32;
    const uint32_t* Qgl = g_qlo + (size_t)bh * T_ * 32 + (size_t)q0 * 32;
    const uint32_t* Kgh = g_khi + (size_t)bh * T_ * 32;
    const uint32_t* Kgl = g_klo + (size_t)bh * T_ * 32;
    const uint32_t* Vgp = g_vp  + (size_t)bh * (T_/2) * HD_;

    const int sub  = lane >> 3, lrow = lane & 7;

    uint32_t kwoff4[2];
#pragma unroll
    for (int np = 0; np < 2; np++)
        kwoff4[np] = (uint32_t)((np * 16 + (sub >> 1) * 8 + lrow) * FQ_LD + (sub & 1) * 4);

    // K cp.async mapping: tid 0-127 -> Kh, 128-255 -> Kl; 2x16B per thread
    const int km = tid >> 7, kr = (tid >> 2) & 31, kcc = tid & 3;
    const uint32_t kdst = (uint32_t)((km ? 1152 : 0) + kr * FQ_LD + kcc * 8) * 4u;
    const uint32_t* kgsrc = km ? Kgl : Kgh;

    // V cp.async mapping: 16 pair-rows x 16 word4-chunks; 1x16B per thread
    const int vtp = tid >> 4, vd4 = tid & 15;
    const uint32_t vdst = (uint32_t)(vtp * FV_LD + vd4 * 4) * 4u;

    const int nkt = 4 * qi + 4;

    // prologue: stage Q, submit K(0)+V(0)
#pragma unroll
    for (int it = 0; it < 4; it++) {
        const int u = tid + it * 256;
        const int r = u >> 3, wc = (u & 7) * 4;
        *(uint4*)&Qh[r * FQ_LD + wc] = *(const uint4*)(Qgh + r * 32 + wc);
        *(uint4*)&Ql[r * FQ_LD + wc] = *(const uint4*)(Qgl + r * 32 + wc);
    }
    CP_ASYNC16(kbase[0] + kdst,      kgsrc + (size_t)kr * 32 + kcc * 8);
    CP_ASYNC16(kbase[0] + kdst + 16, kgsrc + (size_t)kr * 32 + kcc * 8 + 4);
    CP_ASYNC16(vbase[0] + vdst,      Vgp + (size_t)vtp * HD_ + vd4 * 4);
    CP_COMMIT();

    const int rlo = wm * 16 + g;
    const int rhi = rlo + 8;
    __syncthreads();   // Q visible

    // hoist Q fragments (loop-invariant)
    uint32_t qah[4][4], qal[4][4];
    {
        const uint32_t qwoff =
            (uint32_t)((wm * 16 + (sub & 1) * 8 + lrow) * FQ_LD + (sub >> 1) * 4);
#pragma unroll
        for (int ks = 0; ks < 4; ks++) {
            LDSM_X4(qah[ks][0], qah[ks][1], qah[ks][2], qah[ks][3],
                    bQh + (qwoff + ks * 8) * 4u);
            LDSM_X4(qal[ks][0], qal[ks][1], qal[ks][2], qal[ks][3],
                    bQl + (qwoff + ks * 8) * 4u);
        }
    }

    float o[8][4];
#pragma unroll
    for (int nt = 0; nt < 8; nt++)
#pragma unroll
        for (int e = 0; e < 4; e++) o[nt][e] = 0.f;

    float mrun_lo = -INFINITY, mrun_hi = -INFINITY;
    float lrun_lo = 0.f,       lrun_hi = 0.f;

    const int qrow_lo = q0 + rlo;
    const int qrow_hi = q0 + rhi;

#pragma unroll 1
    for (int kt = 0; kt < nkt; kt++) {
        CP_WAIT(0);        // K(kt), V(kt) landed
        __syncthreads();   // visible to all; kt-1 readers done

        if (kt + 1 < nkt) {
            const int s = (kt + 1) & 1;
            CP_ASYNC16(kbase[s] + kdst,
                       kgsrc + (size_t)((kt + 1) * 32 + kr) * 32 + kcc * 8);
            CP_ASYNC16(kbase[s] + kdst + 16,
                       kgsrc + (size_t)((kt + 1) * 32 + kr) * 32 + kcc * 8 + 4);
            CP_ASYNC16(vbase[s] + vdst,
                       Vgp + (size_t)((kt + 1) * 16 + vtp) * HD_ + vd4 * 4);
            CP_COMMIT();
        }

        const uint32_t bKh = kbase[kt & 1];
        const uint32_t bKl = bKh + 1152 * 4;
        const uint32_t* Vp = smu + vword[kt & 1];

        // ---- S = Q @ K^T : 3-term fp16 ----
        float s[4][4];
#pragma unroll
        for (int nt = 0; nt < 4; nt++)
#pragma unroll
            for (int e = 0; e < 4; e++) s[nt][e] = 0.f;

#pragma unroll
        for (int ks = 0; ks < 4; ks++) {
#pragma unroll
            for (int np = 0; np < 2; np++) {
                uint32_t bh0, bh1, bh2, bh3, bl0, bl1, bl2, bl3;
                LDSM_X4(bh0, bh1, bh2, bh3, bKh + (kwoff4[np] + ks * 8) * 4u);
                LDSM_X4(bl0, bl1, bl2, bl3, bKl + (kwoff4[np] + ks * 8) * 4u);
                MMA_F16(s[2*np],   qah[ks][0], qah[ks][1], qah[ks][2], qah[ks][3], bh0, bh1);
                MMA_F16(s[2*np+1], qah[ks][0], qah[ks][1], qah[ks][2], qah[ks][3], bh2, bh3);
                MMA_F16(s[2*np],   qal[ks][0], qal[ks][1], qal[ks][2], qal[ks][3], bh0, bh1);
                MMA_F16(s[2*np+1], qal[ks][0], qal[ks][1], qal[ks][2], qal[ks][3], bh2, bh3);
                MMA_F16(s[2*np],   qah[ks][0], qah[ks][1], qah[ks][2], qah[ks][3], bl0, bl1);
                MMA_F16(s[2*np+1], qah[ks][0], qah[ks][1], qah[ks][2], qah[ks][3], bl2, bl3);
            }
        }

        // ---- scale + causal mask + row max ----
        float mlo = -INFINITY, mhi = -INFINITY;
        const bool needmask = (kt * 32 + 31) > (q0 + wm * 16);
#pragma unroll
        for (int nt = 0; nt < 4; nt++) {
            const int colb = kt * 32 + nt * 8 + 2 * tig;
#pragma unroll
            for (int j = 0; j < 2; j++) {
                float v0 = s[nt][j] * 0.125f;
                float v1 = s[nt][2 + j] * 0.125f;
                if (needmask) {
                    if (colb + j > qrow_lo) v0 = -INFINITY;
                    if (colb + j > qrow_hi) v1 = -INFINITY;
                }
                s[nt][j] = v0;
                s[nt][2 + j] = v1;
                mlo = fmaxf(mlo, v0);
                mhi = fmaxf(mhi, v1);
            }
        }
#pragma unroll
        for (int off = 1; off < 4; off <<= 1) {
            mlo = fmaxf(mlo, __shfl_xor_sync(0xffffffffu, mlo, off));
            mhi = fmaxf(mhi, __shfl_xor_sync(0xffffffffu, mhi, off));
        }

        // ---- online softmax (registers) ----
        const float mnew_lo = fmaxf(mrun_lo, mlo);
        const float mnew_hi = fmaxf(mrun_hi, mhi);
        const float corr_lo = __expf(mrun_lo - mnew_lo);
        const float corr_hi = __expf(mrun_hi - mnew_hi);
        mrun_lo = mnew_lo; mrun_hi = mnew_hi;

        float sumlo = 0.f, sumhi = 0.f;
        uint32_t pah[2][4], pal[2][4];
#pragma unroll
        for (int nt = 0; nt < 4; nt++) {
            float p0 = __expf(s[nt][0] - mnew_lo);
            float p1 = __expf(s[nt][1] - mnew_lo);
            float p2 = __expf(s[nt][2] - mnew_hi);
            float p3 = __expf(s[nt][3] - mnew_hi);
            sumlo += p0 + p1;
            sumhi += p2 + p3;
            const int ks = nt >> 1;
            const int hi2 = (nt & 1) * 2;
            split2h(p0, p1, pah[ks][hi2],     pal[ks][hi2]);
            split2h(p2, p3, pah[ks][hi2 + 1], pal[ks][hi2 + 1]);
        }
#pragma unroll
        for (int off = 1; off < 4; off <<= 1) {
            sumlo += __shfl_xor_sync(0xffffffffu, sumlo, off);
            sumhi += __shfl_xor_sync(0xffffffffu, sumhi, off);
        }
        lrun_lo = lrun_lo * corr_lo + sumlo;
        lrun_hi = lrun_hi * corr_hi + sumhi;

#pragma unroll
        for (int nt = 0; nt < 8; nt++) {
            o[nt][0] *= corr_lo; o[nt][1] *= corr_lo;
            o[nt][2] *= corr_hi; o[nt][3] *= corr_hi;
        }

        // ---- O += P @ V : 2-term fp16, pre-packed fp16 V ----
#pragma unroll
        for (int ks = 0; ks < 2; ks++) {
#pragma unroll
            for (int nt = 0; nt < 8; nt++) {
                const int col = nt * 8 + g;
                const uint32_t vh0 = Vp[(ks * 8 + tig)     * FV_LD + col];
                const uint32_t vh1 = Vp[(ks * 8 + tig + 4) * FV_LD + col];
                MMA_F16(o[nt], pah[ks][0], pah[ks][1], pah[ks][2], pah[ks][3], vh0, vh1);
                MMA_F16(o[nt], pal[ks][0], pal[ks][1], pal[ks][2], pal[ks][3], vh0, vh1);
            }
        }
    }

    // ---- normalize + store fp16-split output ----
    const float inv_lo = 1.f / lrun_lo;
    const float inv_hi = 1.f / lrun_hi;
    const int b = bh >> 4, h = bh & 15;
    const int t_lo = q0 + rlo, t_hi = q0 + rhi;
#pragma unroll
    for (int nt = 0; nt < 8; nt++) {
        const int d = nt * 8 + 2 * tig;
        const int w = (h * HD_ + d) >> 1;
        uint32_t hw, lw;
        split2h(o[nt][0] * inv_lo, o[nt][1] * inv_lo, hw, lw);
        g_ahi[(size_t)(b * T_ + t_lo) * KW_ + w] = hw;
        g_alo[(size_t)(b * T_ + t_lo) * KW_ + w] = lw;
        split2h(o[nt][2] * inv_hi, o[nt][3] * inv_hi, hw, lw);
        g_ahi[(size_t)(b * T_ + t_hi) * KW_ + w] = hw;
        g_alo[(size_t)(b * T_ + t_hi) * KW_ + w] = lw;
    }
}

// ===========================================================================
// Launch
// ===========================================================================
extern "C" void kernel_launch(void* const* d_in, const int* in_sizes, int n_in,
                              void* d_out, int out_size)
{
    const float* x      = (const float*)d_in[0];
    const float* w_attn = (const float*)d_in[1];
    const float* b_attn = (const float*)d_in[2];
    const float* w_proj = (const float*)d_in[3];
    const float* b_proj = (const float*)d_in[4];
    float* out = (float*)d_out;

    uint32_t *xhi, *xlo, *ahi, *alo, *wthi, *wphi, *vp;
    float* v;
    cudaGetSymbolAddress((void**)&xhi,  g_xhi);
    cudaGetSymbolAddress((void**)&xlo,  g_xlo);
    cudaGetSymbolAddress((void**)&ahi,  g_ahi);
    cudaGetSymbolAddress((void**)&alo,  g_alo);
    cudaGetSymbolAddress((void**)&wthi, g_wthi);
    cudaGetSymbolAddress((void**)&wphi, g_wphi);
    cudaGetSymbolAddress((void**)&vp,   g_vp);
    cudaGetSymbolAddress((void**)&v,    g_v);

    cudaFuncSetAttribute(flash_hmma,
                         cudaFuncAttributeMaxDynamicSharedMemorySize, FL_SMEM);
    cudaFuncSetAttribute(hmma_gemm<3072, true>,
                         cudaFuncAttributeMaxDynamicSharedMemorySize, GEMM_SMEM);
    cudaFuncSetAttribute(hmma_gemm<1024, false>,
                         cudaFuncAttributeMaxDynamicSharedMemorySize, GEMM_SMEM);

    // Prologue: fp16-split x; fp16-round both transposed weights
    split_pack_elem_f16<<<(M_*C_/4 + 255)/256, 256>>>(x, xhi, xlo, M_*C_/4);
    transpose_pack_f16<<<dim3(3072/32, 1024/32), 256>>>(w_attn, wthi, 1024, 3072);
    transpose_pack_f16<<<dim3(1024/32, 1024/32), 256>>>(w_proj, wphi, 1024, 1024);

    // QKV GEMM (fp16 2-term, CTA 128x128)
    hmma_gemm<3072, true><<<dim3(3072/128, M_/128), 256, GEMM_SMEM>>>(
        xhi, xlo, wthi, b_attn, nullptr);

    // Pair-pack V to fp16 (T pairs)
    pairpack_v<<<(B_*NH_*(T_/2)*HD_/4 + 255)/256, 256>>>(v, vp, B_*NH_*(T_/2)*HD_/4);

    // Flash attention (fp16), tail-packed grid
    flash_hmma<<<dim3(B_*NH_, T_/128), 256, FL_SMEM>>>();

    // Output projection (fp16 2-term, CTA 128x128)
    hmma_gemm<1024, false><<<dim3(1024/128, M_/128), 256, GEMM_SMEM>>>(
        ahi, alo, wphi, b_proj, out);
}